// round 6
// baseline (speedup 1.0000x reference)
#include <cuda_runtime.h>
#include <cuda_bf16.h>
#include <cstdint>

#define NP 100000
#define NA 50000
#define EPP 1600000
#define EAP 800000
#define EPA 800000

// ---------------- scratch ----------------------------------------------------
__device__ __align__(16) float g_hs[NP * 128];
__device__ __align__(16) float g_tmp[NP * 128];    // zero-on-read invariant
__device__ __align__(16) float g_es[NP * 4];
__device__ __align__(16) float g_ed[3 * NP * 4];
__device__ __align__(16) float g_den[3 * NP * 4];
__device__ __align__(16) float g_accp[NP * 128];
__device__ __align__(16) float g_acca[NA * 128];
__device__ __align__(16) float g_vd1[3 * 128 * 4];
__device__ __align__(16) float g_vd2[3 * 128 * 4];

// ---------------- helpers ----------------------------------------------------
__device__ __forceinline__ float lrelu(float x) { return x > 0.f ? x : 0.2f * x; }

__device__ __forceinline__ void redAdd4(float* p, float4 v) {
    asm volatile("red.global.add.v4.f32 [%0], {%1,%2,%3,%4};"
                 :: "l"(p), "f"(v.x), "f"(v.y), "f"(v.z), "f"(v.w) : "memory");
}

__device__ __forceinline__ unsigned long long pack2(float lo, float hi) {
    unsigned long long r;
    asm("mov.b64 %0, {%1, %2};" : "=l"(r) : "f"(lo), "f"(hi));
    return r;
}
__device__ __forceinline__ void fma2(unsigned long long& d,
                                     unsigned long long a, unsigned long long b) {
    asm("fma.rn.f32x2 %0, %1, %2, %0;" : "+l"(d) : "l"(a), "l"(b));
}
__device__ __forceinline__ float2 unpack2(unsigned long long v) {
    float lo, hi;
    asm("mov.b64 {%0, %1}, %2;" : "=f"(lo), "=f"(hi) : "l"(v));
    return make_float2(lo, hi);
}

// ---------------- SGEMM (f32x2, 8xTN/thread) + fused es epilogue --------------
// C[M,BN] = A[M,128] @ B[128,BN]; es[m,h] = sum_c C[m,h*CC+c]*a_s[h*CC+c]
// BM=128, BK=8, 256 threads, TM=8 rows x TN cols per thread. grid.x == 1.
template <int BN, int TN, int CC>
__global__ void __launch_bounds__(256, 2)
sgemm_es(const float* __restrict__ A, const float* __restrict__ B,
         float* __restrict__ C, float* __restrict__ es,
         const float* __restrict__ a_s, int M) {
    const int K = 128;
    const int BK = 8;
    __shared__ __align__(16) float As[2][BK][128 + 4];  // row 132 floats (528B, 16B-mult)
    __shared__ __align__(16) float Bs[2][BK][BN];
    int tid = threadIdx.x;
    int m0 = blockIdx.y * 128;

    // A loader: 128x8 tile = 1024 floats -> one float4/thread
    int aRow = tid >> 1;
    int aK = (tid & 1) * 4;
    // B loader: 8xBN tile -> one float4/thread for BN=128, half threads for BN=64
    constexpr int BTH = BK * BN / 4;     // 256 or 128
    int bK = tid / (BN / 4);
    int bC = (tid % (BN / 4)) * 4;

    int tx = tid & 15;                   // col group (BN/TN == 16 both cases)
    int ty = tid >> 4;                   // row group (128/8 == 16)

    unsigned long long acc2[4][TN];      // 4 m-pairs x TN cols
#pragma unroll
    for (int ip = 0; ip < 4; ip++)
#pragma unroll
        for (int j = 0; j < TN; j++) acc2[ip][j] = 0ull;

    float4 ra, rb;
    auto loadg = [&](int k0) {
        int m = m0 + aRow;
        ra = (m < M) ? *(const float4*)(A + (size_t)m * K + k0 + aK)
                     : make_float4(0.f, 0.f, 0.f, 0.f);
        if (BTH == 256 || tid < BTH)
            rb = *(const float4*)(B + (size_t)(k0 + bK) * BN + bC);
    };
    auto stores = [&](int buf) {
        As[buf][aK + 0][aRow] = ra.x;
        As[buf][aK + 1][aRow] = ra.y;
        As[buf][aK + 2][aRow] = ra.z;
        As[buf][aK + 3][aRow] = ra.w;
        if (BTH == 256 || tid < BTH)
            *(float4*)&Bs[buf][bK][bC] = rb;
    };

    loadg(0);
    stores(0);
    __syncthreads();

    const int NCH = K / BK;              // 16
#pragma unroll 1
    for (int c = 0; c < NCH; c++) {
        if (c + 1 < NCH) loadg((c + 1) * BK);
        int buf = c & 1;
#pragma unroll
        for (int k = 0; k < BK; k++) {
            // A m-pairs: free repack of LDS.128 quads
            ulonglong2 aLo = *(const ulonglong2*)&As[buf][k][ty * 8];
            ulonglong2 aHi = *(const ulonglong2*)&As[buf][k][ty * 8 + 4];
            unsigned long long ap[4] = {aLo.x, aLo.y, aHi.x, aHi.y};
            float bv[TN];
            {
                float4 b0 = *(const float4*)&Bs[buf][k][tx * TN];
                bv[0] = b0.x; bv[1] = b0.y; bv[2] = b0.z; bv[3] = b0.w;
                if (TN == 8) {
                    float4 b1 = *(const float4*)&Bs[buf][k][tx * TN + 4];
                    bv[4] = b1.x; bv[5] = b1.y; bv[6] = b1.z; bv[7] = b1.w;
                }
            }
            unsigned long long bb[TN];
#pragma unroll
            for (int j = 0; j < TN; j++) bb[j] = pack2(bv[j], bv[j]);
#pragma unroll
            for (int ip = 0; ip < 4; ip++)
#pragma unroll
                for (int j = 0; j < TN; j++) fma2(acc2[ip][j], ap[ip], bb[j]);
        }
        if (c + 1 < NCH) stores((c + 1) & 1);
        __syncthreads();
    }

    float accf[8][TN];
#pragma unroll
    for (int ip = 0; ip < 4; ip++)
#pragma unroll
        for (int j = 0; j < TN; j++) {
            float2 v = unpack2(acc2[ip][j]);
            accf[2 * ip + 0][j] = v.x;
            accf[2 * ip + 1][j] = v.y;
        }

    // es epilogue: thread's TN cols lie in one head; 4 lanes share a head
    {
        float av[TN];
#pragma unroll
        for (int j = 0; j < TN; j++) av[j] = a_s[tx * TN + j];
        int h = (tx * TN) / CC;          // == tx/4 in both configs
#pragma unroll
        for (int i = 0; i < 8; i++) {
            float pv = 0.f;
#pragma unroll
            for (int j = 0; j < TN; j++) pv += accf[i][j] * av[j];
            pv += __shfl_down_sync(0xffffffffu, pv, 2, 4);
            pv += __shfl_down_sync(0xffffffffu, pv, 1, 4);
            int m = m0 + ty * 8 + i;
            if (m < M && (tx & 3) == 0) es[m * 4 + h] = pv;
        }
    }

#pragma unroll
    for (int i = 0; i < 8; i++) {
        int m = m0 + ty * 8 + i;
        if (m < M) {
#pragma unroll
            for (int g = 0; g < TN / 4; g++) {
                float4 o = make_float4(accf[i][g * 4 + 0], accf[i][g * 4 + 1],
                                       accf[i][g * 4 + 2], accf[i][g * 4 + 3]);
                *(float4*)(C + (size_t)m * BN + tx * TN + g * 4) = o;
            }
        }
    }
}

// ---------------- vd folding (both layers, one launch) ------------------------
__global__ void compute_vd(const float* __restrict__ Wd1, const float* __restrict__ ad1,
                           const float* __restrict__ Wd2, const float* __restrict__ ad2,
                           float* __restrict__ vd1, float* __restrict__ vd2) {
    int i = blockIdx.x * blockDim.x + threadIdx.x;
    if (i >= 2 * 3 * 128 * 4) return;
    int layer = i >= 3 * 128 * 4;
    int ii = i - layer * 3 * 128 * 4;
    int h = ii & 3;
    int f = (ii >> 2) & 127;
    int r = ii >> 9;
    int D = layer ? 64 : 128;
    int C = D / 4;
    const float* W = (layer ? Wd2 : Wd1) + (size_t)r * 128 * D + (size_t)f * D + h * C;
    const float* a = (layer ? ad2 : ad1) + r * 4 * C + h * C;
    float s = 0.f;
    for (int c = 0; c < C; c++) s += W[c] * a[c];
    (layer ? vd2 : vd1)[r * 512 + f * 4 + h] = s;
}

// ---------------- ed for TWO relations from one xd pass; zero dens ------------
__global__ void ed_matvec2(const float* __restrict__ x,
                           const float* __restrict__ vdA, const float* __restrict__ vdB,
                           float* __restrict__ edA, float* __restrict__ edB,
                           float* __restrict__ denA, float* __restrict__ denB, int N) {
    int warp = (blockIdx.x * blockDim.x + threadIdx.x) >> 5;
    int lane = threadIdx.x & 31;
    if (warp >= N) return;
    float4 x4 = ((const float4*)x)[(size_t)warp * 32 + lane];
    const float4* vA = (const float4*)vdA;
    const float4* vB = (const float4*)vdB;
    float4 accA = make_float4(0.f, 0.f, 0.f, 0.f), accB = accA;
#pragma unroll
    for (int r = 0; r < 4; r++) {
        float xv = r == 0 ? x4.x : r == 1 ? x4.y : r == 2 ? x4.z : x4.w;
        float4 a = vA[4 * lane + r];
        accA.x += xv * a.x; accA.y += xv * a.y; accA.z += xv * a.z; accA.w += xv * a.w;
        float4 b = vB[4 * lane + r];
        accB.x += xv * b.x; accB.y += xv * b.y; accB.z += xv * b.z; accB.w += xv * b.w;
    }
    for (int off = 16; off; off >>= 1) {
        accA.x += __shfl_down_sync(0xffffffffu, accA.x, off);
        accA.y += __shfl_down_sync(0xffffffffu, accA.y, off);
        accA.z += __shfl_down_sync(0xffffffffu, accA.z, off);
        accA.w += __shfl_down_sync(0xffffffffu, accA.w, off);
        accB.x += __shfl_down_sync(0xffffffffu, accB.x, off);
        accB.y += __shfl_down_sync(0xffffffffu, accB.y, off);
        accB.z += __shfl_down_sync(0xffffffffu, accB.z, off);
        accB.w += __shfl_down_sync(0xffffffffu, accB.w, off);
    }
    if (lane == 0) {
        ((float4*)edA)[warp] = accA;
        ((float4*)edB)[warp] = accB;
        float4 z = make_float4(0.f, 0.f, 0.f, 0.f);
        ((float4*)denA)[warp] = z;
        ((float4*)denB)[warp] = z;
    }
}

// ---------------- ed for ONE relation; zeroes den ------------------------------
__global__ void ed_matvec1(const float* __restrict__ x, const float* __restrict__ vd,
                           float* __restrict__ ed, float* __restrict__ den, int N) {
    int warp = (blockIdx.x * blockDim.x + threadIdx.x) >> 5;
    int lane = threadIdx.x & 31;
    if (warp >= N) return;
    float4 x4 = ((const float4*)x)[(size_t)warp * 32 + lane];
    const float4* v4 = (const float4*)vd;
    float4 acc = make_float4(0.f, 0.f, 0.f, 0.f);
#pragma unroll
    for (int r = 0; r < 4; r++) {
        float xv = r == 0 ? x4.x : r == 1 ? x4.y : r == 2 ? x4.z : x4.w;
        float4 a = v4[4 * lane + r];
        acc.x += xv * a.x; acc.y += xv * a.y; acc.z += xv * a.z; acc.w += xv * a.w;
    }
    for (int off = 16; off; off >>= 1) {
        acc.x += __shfl_down_sync(0xffffffffu, acc.x, off);
        acc.y += __shfl_down_sync(0xffffffffu, acc.y, off);
        acc.z += __shfl_down_sync(0xffffffffu, acc.z, off);
        acc.w += __shfl_down_sync(0xffffffffu, acc.w, off);
    }
    if (lane == 0) {
        ((float4*)ed)[warp] = acc;
        ((float4*)den)[warp] = make_float4(0.f, 0.f, 0.f, 0.f);
    }
}

// ---------------- FUSED edge pass --------------------------------------------
template <int D, int C>
__global__ void edge_fused(const int* __restrict__ src, const int* __restrict__ dst,
                           const float* __restrict__ es, const float* __restrict__ ed,
                           const float* __restrict__ hs, float* __restrict__ tmp,
                           float* __restrict__ den, int E) {
    constexpr int G = D / 4;
    constexpr int LPH = C / 4;
    int gid = blockIdx.x * blockDim.x + threadIdx.x;
    int e = gid / G;
    bool valid = e < E;
    if (!valid) e = 0;
    int lane = threadIdx.x & 31;
    int lg = lane & (G - 1);
    int base = lane - lg;
    int s = src[e], d = dst[e];
    float ee = 0.f;
    if (lg < 4)
        ee = __expf(lrelu(es[s * 4 + lg] + ed[d * 4 + lg]));
    float e0 = __shfl_sync(0xffffffffu, ee, base + 0);
    float e1 = __shfl_sync(0xffffffffu, ee, base + 1);
    float e2 = __shfl_sync(0xffffffffu, ee, base + 2);
    float e3 = __shfl_sync(0xffffffffu, ee, base + 3);
    if (valid && lg == 0)
        redAdd4(den + (size_t)d * 4, make_float4(e0, e1, e2, e3));
    int h = lg / LPH;
    float a = (h == 0) ? e0 : (h == 1) ? e1 : (h == 2) ? e2 : e3;
    float4 v = ((const float4*)hs)[(size_t)s * G + lg];
    if (valid)
        redAdd4(tmp + (size_t)d * D + lg * 4,
                make_float4(v.x * a, v.y * a, v.z * a, v.w * a));
}

// -------- normalize + add + bias/relu; ZEROES tmp for next conv ----------------
template <int C>
__global__ void norm_add(float* __restrict__ tmp, const float* __restrict__ den,
                         float* __restrict__ acc, int N, int D, int add,
                         const float* __restrict__ bias0, const float* __restrict__ bias1,
                         int relu) {
    int i = blockIdx.x * blockDim.x + threadIdx.x;
    int nv = N * (D / 4);
    if (i >= nv) return;
    int d = i / (D / 4);
    int q = i % (D / 4);
    int h = (q * 4) / C;
    float inv = 1.f / (den[d * 4 + h] + 1e-16f);
    float4 t = ((float4*)tmp)[i];
    ((float4*)tmp)[i] = make_float4(0.f, 0.f, 0.f, 0.f);
    float4 o = make_float4(t.x * inv, t.y * inv, t.z * inv, t.w * inv);
    if (add) {
        float4 a = ((const float4*)acc)[i];
        o.x += a.x; o.y += a.y; o.z += a.z; o.w += a.w;
    }
    if (bias0) {
        float4 b = *(const float4*)(bias0 + q * 4);
        o.x += b.x; o.y += b.y; o.z += b.z; o.w += b.w;
    }
    if (bias1) {
        float4 b = *(const float4*)(bias1 + q * 4);
        o.x += b.x; o.y += b.y; o.z += b.z; o.w += b.w;
    }
    if (relu) {
        o.x = fmaxf(o.x, 0.f); o.y = fmaxf(o.y, 0.f);
        o.z = fmaxf(o.z, 0.f); o.w = fmaxf(o.w, 0.f);
    }
    ((float4*)acc)[i] = o;
}

// =============================================================================
extern "C" void kernel_launch(void* const* d_in, const int* in_sizes, int n_in,
                              void* d_out, int out_size) {
    const float* x_p = (const float*)d_in[0];
    const float* x_a = (const float*)d_in[1];
    const int* src_pp = (const int*)d_in[2];
    const int* dst_pp = (const int*)d_in[3];
    const int* src_ap = (const int*)d_in[4];
    const int* dst_ap = (const int*)d_in[5];
    const int* src_pa = (const int*)d_in[6];
    const int* dst_pa = (const int*)d_in[7];
    const float* Wsrc1 = (const float*)d_in[8];
    const float* Wdst1 = (const float*)d_in[9];
    const float* asrc1 = (const float*)d_in[10];
    const float* adst1 = (const float*)d_in[11];
    const float* b1 = (const float*)d_in[12];
    const float* Wsrc2 = (const float*)d_in[13];
    const float* Wdst2 = (const float*)d_in[14];
    const float* asrc2 = (const float*)d_in[15];
    const float* adst2 = (const float*)d_in[16];
    const float* b2 = (const float*)d_in[17];
    float* out = (float*)d_out;

    void* p;
    cudaGetSymbolAddress(&p, g_hs);   float* hs   = (float*)p;
    cudaGetSymbolAddress(&p, g_tmp);  float* tmp  = (float*)p;
    cudaGetSymbolAddress(&p, g_es);   float* es   = (float*)p;
    cudaGetSymbolAddress(&p, g_ed);   float* ed   = (float*)p;
    cudaGetSymbolAddress(&p, g_den);  float* den  = (float*)p;
    cudaGetSymbolAddress(&p, g_accp); float* accp = (float*)p;
    cudaGetSymbolAddress(&p, g_acca); float* acca = (float*)p;
    cudaGetSymbolAddress(&p, g_vd1);  float* vd1  = (float*)p;
    cudaGetSymbolAddress(&p, g_vd2);  float* vd2  = (float*)p;

    float* ed0 = ed;               float* den0 = den;
    float* ed1 = ed + NP * 4;      float* den1 = den + NP * 4;
    float* ed2 = ed + 2 * NP * 4;  float* den2 = den + 2 * NP * 4;

    const int TB = 256;
    auto blocks = [](long long n) { return (int)((n + 255) / 256); };

    compute_vd<<<blocks(2 * 3 * 128 * 4), TB>>>(Wdst1, adst1, Wdst2, adst2, vd1, vd2);

    auto conv = [&](const float* xs, int Ns, int Nd,
                    const int* src, const int* dst, int E,
                    const float* Ws, const float* a_s,
                    float* edr, float* denr,
                    float* acc, int D, bool add,
                    const float* bias0, const float* bias1, int relu) {
        dim3 grid(1, (Ns + 127) / 128);
        if (D == 128)
            sgemm_es<128, 8, 32><<<grid, 256>>>(xs, Ws, hs, es, a_s, Ns);
        else
            sgemm_es<64, 4, 16><<<grid, 256>>>(xs, Ws, hs, es, a_s, Ns);
        if (D == 128)
            edge_fused<128, 32><<<blocks((long long)E * 32), TB>>>(src, dst, es, edr, hs, tmp, denr, E);
        else
            edge_fused<64, 16><<<blocks((long long)E * 16), TB>>>(src, dst, es, edr, hs, tmp, denr, E);
        int nv = Nd * (D / 4);
        if (D == 128)
            norm_add<32><<<blocks(nv), TB>>>(tmp, denr, acc, Nd, D, add, bias0, bias1, relu);
        else
            norm_add<16><<<blocks(nv), TB>>>(tmp, denr, acc, Nd, D, add, bias0, bias1, relu);
    };

    // ---------------- layer 1 (D=128, C=32) ----------------
    ed_matvec2<<<blocks((long long)NP * 32), TB>>>(x_p, vd1 + 0 * 512, vd1 + 1 * 512,
                                                   ed0, ed1, den0, den1, NP);
    ed_matvec1<<<blocks((long long)NA * 32), TB>>>(x_a, vd1 + 2 * 512, ed2, den2, NA);

    conv(x_p, NP, NP, src_pp, dst_pp, EPP,
         Wsrc1 + 0 * 128 * 128, asrc1 + 0 * 128, ed0, den0, accp, 128, false,
         nullptr, nullptr, 0);
    conv(x_a, NA, NP, src_ap, dst_ap, EAP,
         Wsrc1 + 1 * 128 * 128, asrc1 + 1 * 128, ed1, den1, accp, 128, true,
         b1 + 0, b1 + 128, 1);
    conv(x_p, NP, NA, src_pa, dst_pa, EPA,
         Wsrc1 + 2 * 128 * 128, asrc1 + 2 * 128, ed2, den2, acca, 128, false,
         b1 + 256, nullptr, 1);

    // ---------------- layer 2 (D=64, C=16) -> d_out ----------------
    ed_matvec2<<<blocks((long long)NP * 32), TB>>>(accp, vd2 + 0 * 512, vd2 + 1 * 512,
                                                   ed0, ed1, den0, den1, NP);
    ed_matvec1<<<blocks((long long)NA * 32), TB>>>(acca, vd2 + 2 * 512, ed2, den2, NA);

    conv(accp, NP, NP, src_pp, dst_pp, EPP,
         Wsrc2 + 0 * 128 * 64, asrc2 + 0 * 64, ed0, den0, out, 64, false,
         nullptr, nullptr, 0);
    conv(acca, NA, NP, src_ap, dst_ap, EAP,
         Wsrc2 + 1 * 128 * 64, asrc2 + 1 * 64, ed1, den1, out, 64, true,
         b2 + 0, b2 + 64, 0);
    conv(accp, NP, NA, src_pa, dst_pa, EPA,
         Wsrc2 + 2 * 128 * 64, asrc2 + 2 * 64, ed2, den2, out + (size_t)NP * 64, 64, false,
         b2 + 128, nullptr, 0);
}

// round 7
// speedup vs baseline: 1.1129x; 1.1129x over previous
#include <cuda_runtime.h>
#include <cuda_bf16.h>
#include <cuda_fp16.h>
#include <cstdint>

#define NP 100000
#define NA 50000
#define EPP 1600000
#define EAP 800000
#define EPA 800000

// ---------------- scratch ----------------------------------------------------
__device__ __align__(16) __half g_hs[NP * 128];    // transformed src feats (fp16)
__device__ __align__(16) float g_tmp[NP * 128];    // zero-on-read invariant
__device__ __align__(16) float g_es[NP * 4];
__device__ __align__(16) float g_ed[3 * NP * 4];
__device__ __align__(16) float g_den[3 * NP * 4];
__device__ __align__(16) float g_accp[NP * 128];
__device__ __align__(16) float g_acca[NA * 128];
__device__ __align__(16) float g_vd1[3 * 128 * 4];
__device__ __align__(16) float g_vd2[3 * 128 * 4];

// ---------------- helpers ----------------------------------------------------
__device__ __forceinline__ float lrelu(float x) { return x > 0.f ? x : 0.2f * x; }

__device__ __forceinline__ void redAdd4(float* p, float4 v) {
    asm volatile("red.global.add.v4.f32 [%0], {%1,%2,%3,%4};"
                 :: "l"(p), "f"(v.x), "f"(v.y), "f"(v.z), "f"(v.w) : "memory");
}

__device__ __forceinline__ unsigned long long pack2(float lo, float hi) {
    unsigned long long r;
    asm("mov.b64 %0, {%1, %2};" : "=l"(r) : "f"(lo), "f"(hi));
    return r;
}
__device__ __forceinline__ void fma2(unsigned long long& d,
                                     unsigned long long a, unsigned long long b) {
    asm("fma.rn.f32x2 %0, %1, %2, %0;" : "+l"(d) : "l"(a), "l"(b));
}
__device__ __forceinline__ float2 unpack2(unsigned long long v) {
    float lo, hi;
    asm("mov.b64 {%0, %1}, %2;" : "=f"(lo), "=f"(hi) : "l"(v));
    return make_float2(lo, hi);
}

// ---------------- SGEMM (f32x2) + fused es epilogue, fp16 C output ------------
// C[M,N](fp16) = A[M,128] @ B[128,N]; es[m,h] = sum_c Cf[m,h*CC+c]*a_s[h*CC+c]
// 128x64 tile, 256 threads, 8x4/thread (R5 measured-best config).
#define BM 128
#define BN 64
#define BK 16
template <int CC>
__global__ void __launch_bounds__(256)
sgemm_es(const float* __restrict__ A, const float* __restrict__ B,
         __half* __restrict__ C, float* __restrict__ es,
         const float* __restrict__ a_s, int M, int N) {
    const int K = 128;
    __shared__ float As[2][BK][BM + 4];
    __shared__ float Bs[2][BK][BN];
    int tid = threadIdx.x;
    int m0 = blockIdx.y * BM, n0 = blockIdx.x * BN;

    int aRow = tid >> 1;
    int aC4 = (tid & 1) * 2;
    int bK = tid >> 4;
    int bC4 = tid & 15;
    int ty = tid >> 4;
    int tx = tid & 15;

    unsigned long long acc2[4][4];
#pragma unroll
    for (int ip = 0; ip < 4; ip++)
#pragma unroll
        for (int j = 0; j < 4; j++) acc2[ip][j] = 0ull;

    float4 ra0, ra1, rb;
    auto loadg = [&](int k0) {
        int m = m0 + aRow;
        if (m < M) {
            ra0 = *(const float4*)(A + (size_t)m * K + k0 + aC4 * 4);
            ra1 = *(const float4*)(A + (size_t)m * K + k0 + aC4 * 4 + 4);
        } else {
            ra0 = make_float4(0.f, 0.f, 0.f, 0.f);
            ra1 = ra0;
        }
        rb = *(const float4*)(B + (size_t)(k0 + bK) * N + n0 + bC4 * 4);
    };
    auto stores = [&](int buf) {
        As[buf][aC4 * 4 + 0][aRow] = ra0.x;
        As[buf][aC4 * 4 + 1][aRow] = ra0.y;
        As[buf][aC4 * 4 + 2][aRow] = ra0.z;
        As[buf][aC4 * 4 + 3][aRow] = ra0.w;
        As[buf][aC4 * 4 + 4][aRow] = ra1.x;
        As[buf][aC4 * 4 + 5][aRow] = ra1.y;
        As[buf][aC4 * 4 + 6][aRow] = ra1.z;
        As[buf][aC4 * 4 + 7][aRow] = ra1.w;
        *(float4*)&Bs[buf][bK][bC4 * 4] = rb;
    };

    loadg(0);
    stores(0);
    __syncthreads();

    const int NCH = K / BK;
#pragma unroll
    for (int c = 0; c < NCH; c++) {
        if (c + 1 < NCH) loadg((c + 1) * BK);
        int buf = c & 1;
#pragma unroll
        for (int k = 0; k < BK; k++) {
            float4 a0 = *(const float4*)&As[buf][k][ty * 8];
            float4 a1 = *(const float4*)&As[buf][k][ty * 8 + 4];
            float4 b = *(const float4*)&Bs[buf][k][tx * 4];
            unsigned long long ap[4] = {pack2(a0.x, a0.y), pack2(a0.z, a0.w),
                                        pack2(a1.x, a1.y), pack2(a1.z, a1.w)};
            unsigned long long bb[4] = {pack2(b.x, b.x), pack2(b.y, b.y),
                                        pack2(b.z, b.z), pack2(b.w, b.w)};
#pragma unroll
            for (int ip = 0; ip < 4; ip++)
#pragma unroll
                for (int j = 0; j < 4; j++) fma2(acc2[ip][j], ap[ip], bb[j]);
        }
        if (c + 1 < NCH) stores((c + 1) & 1);
        __syncthreads();
    }

    float accf[8][4];
#pragma unroll
    for (int ip = 0; ip < 4; ip++)
#pragma unroll
        for (int j = 0; j < 4; j++) {
            float2 v = unpack2(acc2[ip][j]);
            accf[2 * ip + 0][j] = v.x;
            accf[2 * ip + 1][j] = v.y;
        }

    // es epilogue (fp32 accumulators)
    {
        constexpr int RW = CC / 4;
        float4 a4 = *(const float4*)(a_s + n0 + tx * 4);
        int h = (n0 + tx * 4) / CC;
#pragma unroll
        for (int i = 0; i < 8; i++) {
            float pv = accf[i][0] * a4.x + accf[i][1] * a4.y +
                       accf[i][2] * a4.z + accf[i][3] * a4.w;
#pragma unroll
            for (int off = RW / 2; off > 0; off >>= 1)
                pv += __shfl_down_sync(0xffffffffu, pv, off, RW);
            int m = m0 + ty * 8 + i;
            if (m < M && (tx & (RW - 1)) == 0) es[m * 4 + h] = pv;
        }
    }

    // fp16 C store (8B per row-slice)
#pragma unroll
    for (int i = 0; i < 8; i++) {
        int m = m0 + ty * 8 + i;
        if (m < M) {
            union { __half2 h[2]; uint2 u; } cv;
            cv.h[0] = __floats2half2_rn(accf[i][0], accf[i][1]);
            cv.h[1] = __floats2half2_rn(accf[i][2], accf[i][3]);
            *(uint2*)(C + (size_t)m * N + n0 + tx * 4) = cv.u;
        }
    }
}

// ---------------- vd folding (both layers, one launch) ------------------------
__global__ void compute_vd(const float* __restrict__ Wd1, const float* __restrict__ ad1,
                           const float* __restrict__ Wd2, const float* __restrict__ ad2,
                           float* __restrict__ vd1, float* __restrict__ vd2) {
    int i = blockIdx.x * blockDim.x + threadIdx.x;
    if (i >= 2 * 3 * 128 * 4) return;
    int layer = i >= 3 * 128 * 4;
    int ii = i - layer * 3 * 128 * 4;
    int h = ii & 3;
    int f = (ii >> 2) & 127;
    int r = ii >> 9;
    int D = layer ? 64 : 128;
    int C = D / 4;
    const float* W = (layer ? Wd2 : Wd1) + (size_t)r * 128 * D + (size_t)f * D + h * C;
    const float* a = (layer ? ad2 : ad1) + r * 4 * C + h * C;
    float s = 0.f;
    for (int c = 0; c < C; c++) s += W[c] * a[c];
    (layer ? vd2 : vd1)[r * 512 + f * 4 + h] = s;
}

// -------- ed, thread-per-node, TWO relations, smem vd, f32x2; zeroes dens -----
__global__ void __launch_bounds__(256)
ed_nodes2(const float* __restrict__ x,
          const float* __restrict__ vdA, const float* __restrict__ vdB,
          float* __restrict__ edA, float* __restrict__ edB,
          float* __restrict__ denA, float* __restrict__ denB, int N) {
    __shared__ __align__(16) float sv[1024];   // [0:512) vdA, [512:1024) vdB
    int t = threadIdx.x;
    ((float4*)sv)[t] = (t < 128) ? ((const float4*)vdA)[t]
                                 : ((const float4*)vdB)[t - 128];
    __syncthreads();
    int n = blockIdx.x * blockDim.x + t;
    if (n >= N) return;
    unsigned long long accA[2] = {0ull, 0ull}, accB[2] = {0ull, 0ull};
    const float4* xr = (const float4*)(x + (size_t)n * 128);
#pragma unroll 8
    for (int r = 0; r < 32; r++) {
        float4 xv = xr[r];
#pragma unroll
        for (int j = 0; j < 4; j++) {
            float xs = j == 0 ? xv.x : j == 1 ? xv.y : j == 2 ? xv.z : xv.w;
            unsigned long long xp = pack2(xs, xs);
            ulonglong2 va = *(const ulonglong2*)&sv[(4 * r + j) * 4];
            fma2(accA[0], xp, va.x);
            fma2(accA[1], xp, va.y);
            ulonglong2 vb = *(const ulonglong2*)&sv[512 + (4 * r + j) * 4];
            fma2(accB[0], xp, vb.x);
            fma2(accB[1], xp, vb.y);
        }
    }
    float2 a0 = unpack2(accA[0]), a1 = unpack2(accA[1]);
    float2 b0 = unpack2(accB[0]), b1 = unpack2(accB[1]);
    ((float4*)edA)[n] = make_float4(a0.x, a0.y, a1.x, a1.y);
    ((float4*)edB)[n] = make_float4(b0.x, b0.y, b1.x, b1.y);
    float4 z = make_float4(0.f, 0.f, 0.f, 0.f);
    ((float4*)denA)[n] = z;
    ((float4*)denB)[n] = z;
}

// -------- ed, thread-per-node, ONE relation ------------------------------------
__global__ void __launch_bounds__(256)
ed_nodes1(const float* __restrict__ x, const float* __restrict__ vd,
          float* __restrict__ ed, float* __restrict__ den, int N) {
    __shared__ __align__(16) float sv[512];
    int t = threadIdx.x;
    if (t < 128) ((float4*)sv)[t] = ((const float4*)vd)[t];
    __syncthreads();
    int n = blockIdx.x * blockDim.x + t;
    if (n >= N) return;
    unsigned long long acc[2] = {0ull, 0ull};
    const float4* xr = (const float4*)(x + (size_t)n * 128);
#pragma unroll 8
    for (int r = 0; r < 32; r++) {
        float4 xv = xr[r];
#pragma unroll
        for (int j = 0; j < 4; j++) {
            float xs = j == 0 ? xv.x : j == 1 ? xv.y : j == 2 ? xv.z : xv.w;
            unsigned long long xp = pack2(xs, xs);
            ulonglong2 va = *(const ulonglong2*)&sv[(4 * r + j) * 4];
            fma2(acc[0], xp, va.x);
            fma2(acc[1], xp, va.y);
        }
    }
    float2 a0 = unpack2(acc[0]), a1 = unpack2(acc[1]);
    ((float4*)ed)[n] = make_float4(a0.x, a0.y, a1.x, a1.y);
    ((float4*)den)[n] = make_float4(0.f, 0.f, 0.f, 0.f);
}

// ---------------- FUSED edge pass (fp16 hs gather) -----------------------------
template <int D, int C>
__global__ void edge_fused(const int* __restrict__ src, const int* __restrict__ dst,
                           const float* __restrict__ es, const float* __restrict__ ed,
                           const __half* __restrict__ hs, float* __restrict__ tmp,
                           float* __restrict__ den, int E) {
    constexpr int G = D / 4;
    constexpr int LPH = C / 4;
    int gid = blockIdx.x * blockDim.x + threadIdx.x;
    int e = gid / G;
    bool valid = e < E;
    if (!valid) e = 0;
    int lane = threadIdx.x & 31;
    int lg = lane & (G - 1);
    int base = lane - lg;
    int s = src[e], d = dst[e];
    float ee = 0.f;
    if (lg < 4)
        ee = __expf(lrelu(es[s * 4 + lg] + ed[d * 4 + lg]));
    float e0 = __shfl_sync(0xffffffffu, ee, base + 0);
    float e1 = __shfl_sync(0xffffffffu, ee, base + 1);
    float e2 = __shfl_sync(0xffffffffu, ee, base + 2);
    float e3 = __shfl_sync(0xffffffffu, ee, base + 3);
    if (valid && lg == 0)
        redAdd4(den + (size_t)d * 4, make_float4(e0, e1, e2, e3));
    int h = lg / LPH;
    float a = (h == 0) ? e0 : (h == 1) ? e1 : (h == 2) ? e2 : e3;
    union { uint2 u; __half2 h2[2]; } cv;
    cv.u = *(const uint2*)(hs + (size_t)s * D + lg * 4);
    float2 v01 = __half22float2(cv.h2[0]);
    float2 v23 = __half22float2(cv.h2[1]);
    if (valid)
        redAdd4(tmp + (size_t)d * D + lg * 4,
                make_float4(v01.x * a, v01.y * a, v23.x * a, v23.y * a));
}

// -------- normalize + add + bias/relu; ZEROES tmp for next conv ----------------
template <int C>
__global__ void norm_add(float* __restrict__ tmp, const float* __restrict__ den,
                         float* __restrict__ acc, int N, int D, int add,
                         const float* __restrict__ bias0, const float* __restrict__ bias1,
                         int relu) {
    int i = blockIdx.x * blockDim.x + threadIdx.x;
    int nv = N * (D / 4);
    if (i >= nv) return;
    int d = i / (D / 4);
    int q = i % (D / 4);
    int h = (q * 4) / C;
    float inv = 1.f / (den[d * 4 + h] + 1e-16f);
    float4 t = ((float4*)tmp)[i];
    ((float4*)tmp)[i] = make_float4(0.f, 0.f, 0.f, 0.f);
    float4 o = make_float4(t.x * inv, t.y * inv, t.z * inv, t.w * inv);
    if (add) {
        float4 a = ((const float4*)acc)[i];
        o.x += a.x; o.y += a.y; o.z += a.z; o.w += a.w;
    }
    if (bias0) {
        float4 b = *(const float4*)(bias0 + q * 4);
        o.x += b.x; o.y += b.y; o.z += b.z; o.w += b.w;
    }
    if (bias1) {
        float4 b = *(const float4*)(bias1 + q * 4);
        o.x += b.x; o.y += b.y; o.z += b.z; o.w += b.w;
    }
    if (relu) {
        o.x = fmaxf(o.x, 0.f); o.y = fmaxf(o.y, 0.f);
        o.z = fmaxf(o.z, 0.f); o.w = fmaxf(o.w, 0.f);
    }
    ((float4*)acc)[i] = o;
}

// =============================================================================
extern "C" void kernel_launch(void* const* d_in, const int* in_sizes, int n_in,
                              void* d_out, int out_size) {
    const float* x_p = (const float*)d_in[0];
    const float* x_a = (const float*)d_in[1];
    const int* src_pp = (const int*)d_in[2];
    const int* dst_pp = (const int*)d_in[3];
    const int* src_ap = (const int*)d_in[4];
    const int* dst_ap = (const int*)d_in[5];
    const int* src_pa = (const int*)d_in[6];
    const int* dst_pa = (const int*)d_in[7];
    const float* Wsrc1 = (const float*)d_in[8];
    const float* Wdst1 = (const float*)d_in[9];
    const float* asrc1 = (const float*)d_in[10];
    const float* adst1 = (const float*)d_in[11];
    const float* b1 = (const float*)d_in[12];
    const float* Wsrc2 = (const float*)d_in[13];
    const float* Wdst2 = (const float*)d_in[14];
    const float* asrc2 = (const float*)d_in[15];
    const float* adst2 = (const float*)d_in[16];
    const float* b2 = (const float*)d_in[17];
    float* out = (float*)d_out;

    void* p;
    cudaGetSymbolAddress(&p, g_hs);   __half* hs  = (__half*)p;
    cudaGetSymbolAddress(&p, g_tmp);  float* tmp  = (float*)p;
    cudaGetSymbolAddress(&p, g_es);   float* es   = (float*)p;
    cudaGetSymbolAddress(&p, g_ed);   float* ed   = (float*)p;
    cudaGetSymbolAddress(&p, g_den);  float* den  = (float*)p;
    cudaGetSymbolAddress(&p, g_accp); float* accp = (float*)p;
    cudaGetSymbolAddress(&p, g_acca); float* acca = (float*)p;
    cudaGetSymbolAddress(&p, g_vd1);  float* vd1  = (float*)p;
    cudaGetSymbolAddress(&p, g_vd2);  float* vd2  = (float*)p;

    float* ed0 = ed;               float* den0 = den;
    float* ed1 = ed + NP * 4;      float* den1 = den + NP * 4;
    float* ed2 = ed + 2 * NP * 4;  float* den2 = den + 2 * NP * 4;

    const int TB = 256;
    auto blocks = [](long long n) { return (int)((n + 255) / 256); };

    auto gemm = [&](const float* xs, int Ns, const float* Ws, const float* a_s, int D) {
        dim3 grid(D / 64, (Ns + BM - 1) / BM);
        if (D == 128)
            sgemm_es<32><<<grid, 256>>>(xs, Ws, hs, es, a_s, Ns, D);
        else
            sgemm_es<16><<<grid, 256>>>(xs, Ws, hs, es, a_s, Ns, D);
    };
    auto edge = [&](const int* src, const int* dst, int E, float* edr, float* denr, int D) {
        if (D == 128)
            edge_fused<128, 32><<<blocks((long long)E * 32), TB>>>(src, dst, es, edr, hs, tmp, denr, E);
        else
            edge_fused<64, 16><<<blocks((long long)E * 16), TB>>>(src, dst, es, edr, hs, tmp, denr, E);
    };
    auto norm = [&](float* denr, float* acc, int Nd, int D, int add,
                    const float* bias0, const float* bias1, int relu) {
        int nv = Nd * (D / 4);
        if (D == 128)
            norm_add<32><<<blocks(nv), TB>>>(tmp, denr, acc, Nd, D, add, bias0, bias1, relu);
        else
            norm_add<16><<<blocks(nv), TB>>>(tmp, denr, acc, Nd, D, add, bias0, bias1, relu);
    };

    // ---------------- layer 1 (D=128, C=32) ----------------
    compute_vd<<<blocks(2 * 3 * 128 * 4), TB>>>(Wdst1, adst1, Wdst2, adst2, vd1, vd2);
    gemm(x_p, NP, Wsrc1 + 0 * 128 * 128, asrc1 + 0 * 128, 128);
    ed_nodes2<<<blocks(NP), TB>>>(x_p, vd1 + 0 * 512, vd1 + 1 * 512, ed0, ed1, den0, den1, NP);
    edge(src_pp, dst_pp, EPP, ed0, den0, 128);          // <- target profile slot
    norm(den0, accp, NP, 128, 0, nullptr, nullptr, 0);

    gemm(x_a, NA, Wsrc1 + 1 * 128 * 128, asrc1 + 1 * 128, 128);
    edge(src_ap, dst_ap, EAP, ed1, den1, 128);
    norm(den1, accp, NP, 128, 1, b1 + 0, b1 + 128, 1);

    ed_nodes1<<<blocks(NA), TB>>>(x_a, vd1 + 2 * 512, ed2, den2, NA);
    gemm(x_p, NP, Wsrc1 + 2 * 128 * 128, asrc1 + 2 * 128, 128);
    edge(src_pa, dst_pa, EPA, ed2, den2, 128);
    norm(den2, acca, NA, 128, 0, b1 + 256, nullptr, 1);

    // ---------------- layer 2 (D=64, C=16) -> d_out ----------------
    ed_nodes2<<<blocks(NP), TB>>>(accp, vd2 + 0 * 512, vd2 + 1 * 512, ed0, ed1, den0, den1, NP);
    gemm(accp, NP, Wsrc2 + 0 * 128 * 64, asrc2 + 0 * 64, 64);
    edge(src_pp, dst_pp, EPP, ed0, den0, 64);
    norm(den0, out, NP, 64, 0, nullptr, nullptr, 0);

    gemm(acca, NA, Wsrc2 + 1 * 128 * 64, asrc2 + 1 * 64, 64);
    edge(src_ap, dst_ap, EAP, ed1, den1, 64);
    norm(den1, out, NP, 64, 1, b2 + 0, b2 + 64, 0);

    ed_nodes1<<<blocks(NA), TB>>>(acca, vd2 + 2 * 512, ed2, den2, NA);
    gemm(accp, NP, Wsrc2 + 2 * 128 * 64, asrc2 + 2 * 64, 64);
    edge(src_pa, dst_pa, EPA, ed2, den2, 64);
    norm(den2, out + (size_t)NP * 64, NA, 64, 0, b2 + 128, nullptr, 0);
}